// round 6
// baseline (speedup 1.0000x reference)
#include <cuda_runtime.h>
#include <cuda_bf16.h>

#define N_NODES 50000
#define N_EDGES 800000
#define FD      128                   // feature dim
#define NF4     (N_NODES * (FD/4))    // float4 count of a node matrix

// ---- scratch (static __device__ arrays: allocation-free) ----
__device__ __align__(16) float g_node [N_NODES * FD];  // current node embeddings
__device__ __align__(16) float g_emean[N_NODES * FD];  // edge mean by src (layer-invariant)
__device__ __align__(16) float g_h    [N_NODES * FD];  // EdgeSAGE hidden
__device__ __align__(16) float g_tmp  [N_NODES * FD];  // neighbor mean
__device__ int g_cnt_d[N_NODES];                       // in-degree counts
__device__ int g_cnt_s[N_NODES];                       // out-degree counts
__device__ int g_off_d[N_NODES];                       // dst CSR range begin (unordered alloc)
__device__ int g_off_s[N_NODES];                       // src CSR range begin
__device__ int g_cur_d[N_NODES];                       // fill cursors
__device__ int g_cur_s[N_NODES];
__device__ int g_lst_d[N_EDGES];                       // edge ids grouped by dst
__device__ int g_src_d[N_EDGES];                       // src node of those edges
__device__ int g_lst_s[N_EDGES];                       // edge ids grouped by src
__device__ int g_tot_d;                                // range allocator totals
__device__ int g_tot_s;
__device__ int g_mode;                                 // 0 = int32 indices, 1 = int64

// ---- detect index dtype: int64 values < 2^31 have zero high words ----
__global__ void k_detect(const int* __restrict__ idx32) {
    if (blockIdx.x == 0 && threadIdx.x == 0) {
        int nz = 0;
        for (int i = 0; i < 512; i++) nz += (idx32[2 * i + 1] != 0);
        g_mode = (nz == 0) ? 1 : 0;
    }
}

__device__ __forceinline__ void load_sd(const void* __restrict__ idx, int e,
                                        int& s, int& d) {
    if (g_mode) {
        const long long* p = (const long long*)idx;
        s = (int)p[e]; d = (int)p[e + N_EDGES];
    } else {
        const int* p = (const int*)idx;
        s = p[e]; d = p[e + N_EDGES];
    }
    s = min(max(s, 0), N_NODES - 1);
    d = min(max(d, 0), N_NODES - 1);
}

// ---- CSR build: zero counts + totals ----
__global__ void k_zero_cnt() {
    int i = blockIdx.x * blockDim.x + threadIdx.x;
    if (i < N_NODES) { g_cnt_d[i] = 0; g_cnt_s[i] = 0; }
    if (i == 0) { g_tot_d = 0; g_tot_s = 0; }
}

// ---- CSR build: histogram ----
__global__ void k_hist(const void* __restrict__ idx) {
    int e = blockIdx.x * blockDim.x + threadIdx.x;
    if (e >= N_EDGES) return;
    int s, d; load_sd(idx, e, s, d);
    atomicAdd(&g_cnt_d[d], 1);
    atomicAdd(&g_cnt_s[s], 1);
}

// ---- CSR build: allocate a private range per node (order irrelevant) ----
__global__ void k_alloc() {
    int i = blockIdx.x * blockDim.x + threadIdx.x;
    if (i >= N_NODES) return;
    int cd = g_cnt_d[i];
    int od = atomicAdd(&g_tot_d, cd);
    g_off_d[i] = od;
    g_cur_d[i] = od;
    int cs = g_cnt_s[i];
    int os = atomicAdd(&g_tot_s, cs);
    g_off_s[i] = os;
    g_cur_s[i] = os;
}

// ---- CSR build: fill lists ----
__global__ void k_fill(const void* __restrict__ idx) {
    int e = blockIdx.x * blockDim.x + threadIdx.x;
    if (e >= N_EDGES) return;
    int s, d; load_sd(idx, e, s, d);
    int pd = atomicAdd(&g_cur_d[d], 1);
    pd = min(max(pd, 0), N_EDGES - 1);
    g_lst_d[pd] = e;
    g_src_d[pd] = s;
    int ps = atomicAdd(&g_cur_s[s], 1);
    ps = min(max(ps, 0), N_EDGES - 1);
    g_lst_s[ps] = e;
}

// ---- pass 1: both segment means via gather (warp per node) ----
__global__ void k_gather_means(const float* __restrict__ ea) {
    int gid = blockIdx.x * blockDim.x + threadIdx.x;
    int w = gid >> 5, lane = gid & 31;
    if (w >= N_NODES) return;
    const float4* ea4 = (const float4*)ea;

    // mean of edge_attr over incoming edges (by dst) -> g_node
    {
        int b = g_off_d[w];
        int n = g_cnt_d[w];
        int e = min(b + n, N_EDGES);
        float4 acc = make_float4(0.f, 0.f, 0.f, 0.f);
        for (int i = b; i < e; i++) {
            int eid = min(max(g_lst_d[i], 0), N_EDGES - 1);
            float4 v = ea4[(size_t)eid * 32 + lane];
            acc.x += v.x; acc.y += v.y; acc.z += v.z; acc.w += v.w;
        }
        float inv = 1.0f / fmaxf((float)n, 1.0f);
        acc.x *= inv; acc.y *= inv; acc.z *= inv; acc.w *= inv;
        ((float4*)g_node)[w * 32 + lane] = acc;
    }
    // mean of edge_attr over outgoing edges (by src) -> g_emean
    {
        int b = g_off_s[w];
        int n = g_cnt_s[w];
        int e = min(b + n, N_EDGES);
        float4 acc = make_float4(0.f, 0.f, 0.f, 0.f);
        for (int i = b; i < e; i++) {
            int eid = min(max(g_lst_s[i], 0), N_EDGES - 1);
            float4 v = ea4[(size_t)eid * 32 + lane];
            acc.x += v.x; acc.y += v.y; acc.z += v.z; acc.w += v.w;
        }
        float inv = 1.0f / fmaxf((float)n, 1.0f);
        acc.x *= inv; acc.y *= inv; acc.z *= inv; acc.w *= inv;
        ((float4*)g_emean)[w * 32 + lane] = acc;
    }
}

// ---- neighbor mean: tmp[n] = mean over in-edges of h[src(e)] ----
__global__ void k_gather_neigh() {
    int gid = blockIdx.x * blockDim.x + threadIdx.x;
    int w = gid >> 5, lane = gid & 31;
    if (w >= N_NODES) return;
    const float4* h4 = (const float4*)g_h;
    int b = g_off_d[w];
    int n = g_cnt_d[w];
    int e = min(b + n, N_EDGES);
    float4 acc = make_float4(0.f, 0.f, 0.f, 0.f);
    for (int i = b; i < e; i++) {
        int s = min(max(g_src_d[i], 0), N_NODES - 1);
        float4 v = h4[(size_t)s * 32 + lane];
        acc.x += v.x; acc.y += v.y; acc.z += v.z; acc.w += v.w;
    }
    float inv = 1.0f / fmaxf((float)n, 1.0f);
    acc.x *= inv; acc.y *= inv; acc.z *= inv; acc.w *= inv;
    ((float4*)g_tmp)[w * 32 + lane] = acc;
}

// ---- out = relu([A|B] @ W + bias); sel picks buffers ----
// sel 0: A=g_node, B=g_emean, out=g_h
// sel 1: A=g_h,    B=g_tmp,   out=g_node  (+ optional mirror to out2)
// BM=128, BN=128, BK=16, 256 threads, 8x8 per thread
__global__ void __launch_bounds__(256) k_gemm_relu(
        const float* __restrict__ W, const float* __restrict__ bias, int sel,
        float* __restrict__ out2) {
    const float* A;
    const float* B;
    float* out;
    if (sel == 0) { A = g_node; B = g_emean; out = g_h; }
    else          { A = g_h;    B = g_tmp;   out = g_node; }

    __shared__ float As[16][132];   // padded stride kills STS bank conflicts
    __shared__ float Bs[16][128];
    int tid = threadIdx.x;
    int m0  = blockIdx.x * 128;
    int ty = tid >> 4;        // 0..15 (row group of 8)
    int tx = tid & 15;        // 0..15 (col group of 8)

    int arow  = tid >> 2;     // 0..63 (two rows per thread: arow, arow+64)
    int acol4 = tid & 3;      // which float4 of 16-wide k chunk
    int brow  = tid >> 4;     // 0..15
    int bcol  = (tid & 15) * 8;

    float acc[8][8];
    #pragma unroll
    for (int i = 0; i < 8; i++)
        #pragma unroll
        for (int j = 0; j < 8; j++) acc[i][j] = 0.f;

    #pragma unroll 1
    for (int kt = 0; kt < 16; kt++) {
        int kbase = kt * 16;
        const float* Xsrc = (kbase < 128) ? A : B;
        int koff = kbase & 127;

        #pragma unroll
        for (int h = 0; h < 2; h++) {
            int r   = arow + h * 64;
            int row = m0 + r;
            float4 av = make_float4(0.f,0.f,0.f,0.f);
            if (row < N_NODES)
                av = *(const float4*)(Xsrc + (size_t)row * FD + koff + acol4 * 4);
            As[acol4*4+0][r] = av.x;
            As[acol4*4+1][r] = av.y;
            As[acol4*4+2][r] = av.z;
            As[acol4*4+3][r] = av.w;
        }

        float4 b0 = *(const float4*)(W + (size_t)(kbase + brow) * FD + bcol);
        float4 b1 = *(const float4*)(W + (size_t)(kbase + brow) * FD + bcol + 4);
        *(float4*)&Bs[brow][bcol]     = b0;
        *(float4*)&Bs[brow][bcol + 4] = b1;

        __syncthreads();

        #pragma unroll
        for (int kk = 0; kk < 16; kk++) {
            float a[8], b[8];
            *(float4*)&a[0] = *(const float4*)&As[kk][ty*8];
            *(float4*)&a[4] = *(const float4*)&As[kk][ty*8 + 4];
            *(float4*)&b[0] = *(const float4*)&Bs[kk][tx*8];
            *(float4*)&b[4] = *(const float4*)&Bs[kk][tx*8 + 4];
            #pragma unroll
            for (int i = 0; i < 8; i++)
                #pragma unroll
                for (int j = 0; j < 8; j++)
                    acc[i][j] = fmaf(a[i], b[j], acc[i][j]);
        }
        __syncthreads();
    }

    float4 bia0 = *(const float4*)(bias + tx * 8);
    float4 bia1 = *(const float4*)(bias + tx * 8 + 4);
    #pragma unroll
    for (int i = 0; i < 8; i++) {
        int row = m0 + ty * 8 + i;
        if (row < N_NODES) {
            float4 o0, o1;
            o0.x = fmaxf(acc[i][0] + bia0.x, 0.f);
            o0.y = fmaxf(acc[i][1] + bia0.y, 0.f);
            o0.z = fmaxf(acc[i][2] + bia0.z, 0.f);
            o0.w = fmaxf(acc[i][3] + bia0.w, 0.f);
            o1.x = fmaxf(acc[i][4] + bia1.x, 0.f);
            o1.y = fmaxf(acc[i][5] + bia1.y, 0.f);
            o1.z = fmaxf(acc[i][6] + bia1.z, 0.f);
            o1.w = fmaxf(acc[i][7] + bia1.w, 0.f);
            *(float4*)(out + (size_t)row * FD + tx * 8)     = o0;
            *(float4*)(out + (size_t)row * FD + tx * 8 + 4) = o1;
            if (out2) {
                *(float4*)(out2 + (size_t)row * FD + tx * 8)     = o0;
                *(float4*)(out2 + (size_t)row * FD + tx * 8 + 4) = o1;
            }
        }
    }
}

// ---- final: edge embeddings + logits (warp per edge); node emb from g_node ----
__global__ void k_edge_out(const void* __restrict__ idx,
                           const float* __restrict__ Wf,
                           const float* __restrict__ bf,
                           float* __restrict__ logits,
                           float* __restrict__ emb) {
    int gid = blockIdx.x * blockDim.x + threadIdx.x;
    if (gid >= N_EDGES * 32) return;
    int e = gid >> 5, lane = gid & 31;
    int s, d; load_sd(idx, e, s, d);
    float4 sv = ((const float4*)g_node)[(size_t)s * 32 + lane];
    float4 dv = ((const float4*)g_node)[(size_t)d * 32 + lane];
    ((float4*)emb)[(size_t)e * 64 + lane]      = sv;
    ((float4*)emb)[(size_t)e * 64 + 32 + lane] = dv;
    const float4* wf4 = (const float4*)Wf;
    float4 w0 = __ldg(wf4 + lane);
    float4 w1 = __ldg(wf4 + 32 + lane);
    float p = sv.x*w0.x + sv.y*w0.y + sv.z*w0.z + sv.w*w0.w
            + dv.x*w1.x + dv.y*w1.y + dv.z*w1.z + dv.w*w1.w;
    #pragma unroll
    for (int o = 16; o > 0; o >>= 1) p += __shfl_down_sync(0xffffffffu, p, o);
    if (lane == 0) logits[e] = p + bf[0];
}

extern "C" void kernel_launch(void* const* d_in, const int* in_sizes, int n_in,
                              void* d_out, int out_size) {
    const float* edge_attr = (const float*)d_in[0];
    const void*  eidx      = d_in[1];                 // int32 or int64, detected on device
    const float* W0e = (const float*)d_in[2];
    const float* b0e = (const float*)d_in[3];
    const float* W0n = (const float*)d_in[4];
    const float* b0n = (const float*)d_in[5];
    const float* W1e = (const float*)d_in[6];
    const float* b1e = (const float*)d_in[7];
    const float* W1n = (const float*)d_in[8];
    const float* b1n = (const float*)d_in[9];
    const float* Wf  = (const float*)d_in[10];
    const float* bf  = (const float*)d_in[11];

    float* out_logits = (float*)d_out;
    float* out_emb    = out_logits + N_EDGES;
    float* out_node   = out_emb + (size_t)N_EDGES * 2 * FD;

    const int TB = 256;
    int gn   = (N_NODES + TB - 1) / TB;             // per-node grids
    int ge   = (N_EDGES + TB - 1) / TB;             // per-edge grids
    int gw   = (N_NODES * 32 + TB - 1) / TB;        // warp-per-node grids
    int gsc  = (N_EDGES * 32 + TB - 1) / TB;        // warp-per-edge grids
    int ggm  = (N_NODES + 127) / 128;               // 391 gemm blocks

    // CSR build (scan-free: atomic range allocation)
    k_detect<<<1, 32>>>((const int*)eidx);
    k_zero_cnt<<<gn, TB>>>();
    k_hist<<<ge, TB>>>(eidx);
    k_alloc<<<gn, TB>>>();
    k_fill<<<ge, TB>>>(eidx);

    // initial means (node_attr by dst, emean by src)
    k_gather_means<<<gw, TB>>>(edge_attr);

    // layer 0
    k_gemm_relu<<<ggm, TB>>>(W0e, b0e, 0, nullptr);
    k_gather_neigh<<<gw, TB>>>();
    k_gemm_relu<<<ggm, TB>>>(W0n, b0n, 1, nullptr);

    // layer 1
    k_gemm_relu<<<ggm, TB>>>(W1e, b1e, 0, nullptr);
    k_gather_neigh<<<gw, TB>>>();
    k_gemm_relu<<<ggm, TB>>>(W1n, b1n, 1, out_node);  // fused node-embedding output

    // outputs
    k_edge_out<<<gsc, TB>>>(eidx, Wf, bf, out_logits, out_emb);
}

// round 8
// speedup vs baseline: 1.2342x; 1.2342x over previous
#include <cuda_runtime.h>
#include <cuda_bf16.h>
#include <cstdint>

#define N_NODES 50000
#define N_EDGES 800000
#define FD      128
#define NF4     (N_NODES * (FD/4))

// ---- scratch (static __device__ arrays: allocation-free) ----
__device__ __align__(16) float g_node [N_NODES * FD];
__device__ __align__(16) float g_emean[N_NODES * FD];
__device__ __align__(16) float g_h    [N_NODES * FD];
__device__ __align__(16) float g_tmp  [N_NODES * FD];
__device__ __align__(16) __nv_bfloat16 g_wh[4 * 256 * 128];  // W hi, [n][k] transposed
__device__ __align__(16) __nv_bfloat16 g_wl[4 * 256 * 128];  // W lo
__device__ int g_cnt_d[N_NODES];
__device__ int g_cnt_s[N_NODES];
__device__ int g_off_d[N_NODES];
__device__ int g_off_s[N_NODES];
__device__ int g_cur_d[N_NODES];
__device__ int g_cur_s[N_NODES];
__device__ int g_lst_d[N_EDGES];
__device__ int g_src_d[N_EDGES];
__device__ int g_lst_s[N_EDGES];
__device__ int g_tot_d;
__device__ int g_tot_s;
__device__ int g_mode;

// ======================= helpers =======================
__device__ __forceinline__ uint32_t smem_u32(const void* p) {
    uint32_t a;
    asm("{ .reg .u64 t; cvta.to.shared.u64 t, %1; cvt.u32.u64 %0, t; }"
        : "=r"(a) : "l"(p));
    return a;
}

__device__ __forceinline__ void ldm_x4(uint32_t& r0, uint32_t& r1, uint32_t& r2,
                                       uint32_t& r3, uint32_t addr) {
    asm volatile("ldmatrix.sync.aligned.m8n8.x4.shared.b16 {%0,%1,%2,%3}, [%4];"
                 : "=r"(r0), "=r"(r1), "=r"(r2), "=r"(r3) : "r"(addr));
}

__device__ __forceinline__ void mma16816(float& d0, float& d1, float& d2, float& d3,
                                         uint32_t a0, uint32_t a1, uint32_t a2, uint32_t a3,
                                         uint32_t b0, uint32_t b1) {
    asm volatile("mma.sync.aligned.m16n8k16.row.col.f32.bf16.bf16.f32 "
                 "{%0,%1,%2,%3}, {%4,%5,%6,%7}, {%8,%9}, {%0,%1,%2,%3};"
                 : "+f"(d0), "+f"(d1), "+f"(d2), "+f"(d3)
                 : "r"(a0), "r"(a1), "r"(a2), "r"(a3), "r"(b0), "r"(b1));
}

// ======================= graph preprocessing =======================
__global__ void k_detect(const int* __restrict__ idx32) {
    if (blockIdx.x == 0 && threadIdx.x == 0) {
        int nz = 0;
        for (int i = 0; i < 512; i++) nz += (idx32[2 * i + 1] != 0);
        g_mode = (nz == 0) ? 1 : 0;
    }
}

__device__ __forceinline__ void load_sd(const void* __restrict__ idx, int e,
                                        int& s, int& d) {
    if (g_mode) {
        const long long* p = (const long long*)idx;
        s = (int)p[e]; d = (int)p[e + N_EDGES];
    } else {
        const int* p = (const int*)idx;
        s = p[e]; d = p[e + N_EDGES];
    }
    s = min(max(s, 0), N_NODES - 1);
    d = min(max(d, 0), N_NODES - 1);
}

__global__ void k_zero_cnt() {
    int i = blockIdx.x * blockDim.x + threadIdx.x;
    if (i < N_NODES) { g_cnt_d[i] = 0; g_cnt_s[i] = 0; }
    if (i == 0) { g_tot_d = 0; g_tot_s = 0; }
}

__global__ void k_hist(const void* __restrict__ idx) {
    int e = blockIdx.x * blockDim.x + threadIdx.x;
    if (e >= N_EDGES) return;
    int s, d; load_sd(idx, e, s, d);
    atomicAdd(&g_cnt_d[d], 1);
    atomicAdd(&g_cnt_s[s], 1);
}

__global__ void k_alloc() {
    int i = blockIdx.x * blockDim.x + threadIdx.x;
    if (i >= N_NODES) return;
    int cd = g_cnt_d[i];
    int od = atomicAdd(&g_tot_d, cd);
    g_off_d[i] = od;
    g_cur_d[i] = od;
    int cs = g_cnt_s[i];
    int os = atomicAdd(&g_tot_s, cs);
    g_off_s[i] = os;
    g_cur_s[i] = os;
}

__global__ void k_fill(const void* __restrict__ idx) {
    int e = blockIdx.x * blockDim.x + threadIdx.x;
    if (e >= N_EDGES) return;
    int s, d; load_sd(idx, e, s, d);
    int pd = atomicAdd(&g_cur_d[d], 1);
    pd = min(max(pd, 0), N_EDGES - 1);
    g_lst_d[pd] = e;
    g_src_d[pd] = s;
    int ps = atomicAdd(&g_cur_s[s], 1);
    ps = min(max(ps, 0), N_EDGES - 1);
    g_lst_s[ps] = e;
}

__global__ void k_gather_means(const float* __restrict__ ea) {
    int gid = blockIdx.x * blockDim.x + threadIdx.x;
    int w = gid >> 5, lane = gid & 31;
    if (w >= N_NODES) return;
    const float4* ea4 = (const float4*)ea;
    {
        int b = g_off_d[w];
        int n = g_cnt_d[w];
        int e = min(b + n, N_EDGES);
        float4 acc = make_float4(0.f, 0.f, 0.f, 0.f);
        for (int i = b; i < e; i++) {
            int eid = min(max(g_lst_d[i], 0), N_EDGES - 1);
            float4 v = ea4[(size_t)eid * 32 + lane];
            acc.x += v.x; acc.y += v.y; acc.z += v.z; acc.w += v.w;
        }
        float inv = 1.0f / fmaxf((float)n, 1.0f);
        acc.x *= inv; acc.y *= inv; acc.z *= inv; acc.w *= inv;
        ((float4*)g_node)[w * 32 + lane] = acc;
    }
    {
        int b = g_off_s[w];
        int n = g_cnt_s[w];
        int e = min(b + n, N_EDGES);
        float4 acc = make_float4(0.f, 0.f, 0.f, 0.f);
        for (int i = b; i < e; i++) {
            int eid = min(max(g_lst_s[i], 0), N_EDGES - 1);
            float4 v = ea4[(size_t)eid * 32 + lane];
            acc.x += v.x; acc.y += v.y; acc.z += v.z; acc.w += v.w;
        }
        float inv = 1.0f / fmaxf((float)n, 1.0f);
        acc.x *= inv; acc.y *= inv; acc.z *= inv; acc.w *= inv;
        ((float4*)g_emean)[w * 32 + lane] = acc;
    }
}

__global__ void k_gather_neigh() {
    int gid = blockIdx.x * blockDim.x + threadIdx.x;
    int w = gid >> 5, lane = gid & 31;
    if (w >= N_NODES) return;
    const float4* h4 = (const float4*)g_h;
    int b = g_off_d[w];
    int n = g_cnt_d[w];
    int e = min(b + n, N_EDGES);
    float4 acc = make_float4(0.f, 0.f, 0.f, 0.f);
    for (int i = b; i < e; i++) {
        int s = min(max(g_src_d[i], 0), N_NODES - 1);
        float4 v = h4[(size_t)s * 32 + lane];
        acc.x += v.x; acc.y += v.y; acc.z += v.z; acc.w += v.w;
    }
    float inv = 1.0f / fmaxf((float)n, 1.0f);
    acc.x *= inv; acc.y *= inv; acc.z *= inv; acc.w *= inv;
    ((float4*)g_tmp)[w * 32 + lane] = acc;
}

// ======================= W pre-conversion =======================
// W [256 k][128 n] fp32 -> g_wh/g_wl [128 n][256 k] bf16 (hi/lo split), coalesced writes
__global__ void k_prep_w(const float* __restrict__ W, int slot) {
    int idx = blockIdx.x * blockDim.x + threadIdx.x;
    if (idx >= 256 * 128) return;
    int n = idx >> 8, k = idx & 255;
    float x = W[k * 128 + n];
    __nv_bfloat16 hi = __float2bfloat16_rn(x);
    __nv_bfloat16 lo = __float2bfloat16_rn(x - __bfloat162float(hi));
    g_wh[slot * 32768 + n * 256 + k] = hi;
    g_wl[slot * 32768 + n * 256 + k] = lo;
}

// ======================= bf16 split-precision HMMA GEMM =======================
// out = relu([A|B] @ W + bias), tile 128x128, K=256 in 8 chunks of 32.
// sel 0: A=g_node, B=g_emean, out=g_h ; sel 1: A=g_h, B=g_tmp, out=g_node (+out2)
#define SROW 40   // smem row stride in bf16 (80 B: 16B-aligned rows, conflict-free ldmatrix)
__global__ void __launch_bounds__(256) k_gemm_mma(
        int slot, const float* __restrict__ bias, int sel, float* __restrict__ out2) {
    const float* A;
    const float* Bm;
    float* out;
    if (sel == 0) { A = g_node; Bm = g_emean; out = g_h; }
    else          { A = g_h;    Bm = g_tmp;   out = g_node; }
    const __nv_bfloat16* Wh = g_wh + (size_t)slot * 32768;
    const __nv_bfloat16* Wl = g_wl + (size_t)slot * 32768;

    __shared__ __align__(16) __nv_bfloat16 Ah[128 * SROW];
    __shared__ __align__(16) __nv_bfloat16 Al[128 * SROW];
    __shared__ __align__(16) __nv_bfloat16 Bh[128 * SROW];
    __shared__ __align__(16) __nv_bfloat16 Bl[128 * SROW];

    int tid  = threadIdx.x;
    int lane = tid & 31;
    int wid  = tid >> 5;
    int m0   = blockIdx.x * 128;
    int warp_m = wid >> 2;       // 0..1  -> 64 rows each
    int warp_n = wid & 3;        // 0..3  -> 32 cols each

    // ldmatrix lane->coordinate offsets
    int l7 = lane & 7;
    int a_ro = l7 + ((lane >> 3) & 1) * 8;   // row within m16 tile
    int a_ko = (lane >> 4) * 8;              // k within k16
    int b_no = l7 + (lane >> 4) * 8;         // n within n16 pair
    int b_ko = ((lane >> 3) & 1) * 8;        // k within k16

    float acc[4][4][4];
    #pragma unroll
    for (int i = 0; i < 4; i++)
        #pragma unroll
        for (int j = 0; j < 4; j++)
            #pragma unroll
            for (int r = 0; r < 4; r++) acc[i][j][r] = 0.f;

    #pragma unroll 1
    for (int ch = 0; ch < 8; ch++) {
        int kbase = ch * 32;
        const float* X = (kbase < 128) ? A : Bm;
        int koff = kbase & 127;

        // fill A hi/lo: [128 m][32 k] bf16 from fp32
        #pragma unroll
        for (int f = tid; f < 1024; f += 256) {
            int row = f >> 3, q = f & 7;          // k = q*4
            int grow = m0 + row;
            float4 v = make_float4(0.f, 0.f, 0.f, 0.f);
            if (grow < N_NODES)
                v = *(const float4*)(X + (size_t)grow * FD + koff + q * 4);
            __nv_bfloat162 h0 = __float22bfloat162_rn(make_float2(v.x, v.y));
            __nv_bfloat162 h1 = __float22bfloat162_rn(make_float2(v.z, v.w));
            float2 f0 = __bfloat1622float2(h0);
            float2 f1 = __bfloat1622float2(h1);
            __nv_bfloat162 l0 = __float22bfloat162_rn(make_float2(v.x - f0.x, v.y - f0.y));
            __nv_bfloat162 l1 = __float22bfloat162_rn(make_float2(v.z - f1.x, v.w - f1.y));
            uint2 uh, ul;
            uh.x = *(uint32_t*)&h0; uh.y = *(uint32_t*)&h1;
            ul.x = *(uint32_t*)&l0; ul.y = *(uint32_t*)&l1;
            *(uint2*)&Ah[row * SROW + q * 4] = uh;
            *(uint2*)&Al[row * SROW + q * 4] = ul;
        }
        // fill B hi/lo: [128 n][32 k] bf16, straight copy from pre-transposed W
        #pragma unroll
        for (int f = tid; f < 1024; f += 256) {
            int n = f >> 3, q = f & 7;
            *(uint2*)&Bh[n * SROW + q * 4] = *(const uint2*)(Wh + n * 256 + kbase + q * 4);
            *(uint2*)&Bl[n * SROW + q * 4] = *(const uint2*)(Wl + n * 256 + kbase + q * 4);
        }
        __syncthreads();

        #pragma unroll
        for (int ks = 0; ks < 2; ks++) {
            int kl = ks * 16;
            // B fragments: 4 n8 tiles = 2 ldmatrix.x4 per (hi, lo)
            uint32_t bh[2][4], bl[2][4];
            #pragma unroll
            for (int jp = 0; jp < 2; jp++) {
                int nn = warp_n * 32 + jp * 16 + b_no;
                int kk = kl + b_ko;
                ldm_x4(bh[jp][0], bh[jp][1], bh[jp][2], bh[jp][3],
                       smem_u32(&Bh[nn * SROW + kk]));
                ldm_x4(bl[jp][0], bl[jp][1], bl[jp][2], bl[jp][3],
                       smem_u32(&Bl[nn * SROW + kk]));
            }
            #pragma unroll
            for (int i = 0; i < 4; i++) {
                int row = warp_m * 64 + i * 16 + a_ro;
                int kk  = kl + a_ko;
                uint32_t ah0, ah1, ah2, ah3, al0, al1, al2, al3;
                ldm_x4(ah0, ah1, ah2, ah3, smem_u32(&Ah[row * SROW + kk]));
                ldm_x4(al0, al1, al2, al3, smem_u32(&Al[row * SROW + kk]));
                #pragma unroll
                for (int j = 0; j < 4; j++) {
                    uint32_t b0h = bh[j >> 1][(j & 1) * 2], b1h = bh[j >> 1][(j & 1) * 2 + 1];
                    uint32_t b0l = bl[j >> 1][(j & 1) * 2], b1l = bl[j >> 1][(j & 1) * 2 + 1];
                    float* c = acc[i][j];
                    mma16816(c[0], c[1], c[2], c[3], ah0, ah1, ah2, ah3, b0h, b1h);
                    mma16816(c[0], c[1], c[2], c[3], ah0, ah1, ah2, ah3, b0l, b1l);
                    mma16816(c[0], c[1], c[2], c[3], al0, al1, al2, al3, b0h, b1h);
                }
            }
        }
        __syncthreads();
    }

    // epilogue: bias + relu + store (float2 per fragment half)
    int gID = lane >> 2, tig = lane & 3;
    #pragma unroll
    for (int j = 0; j < 4; j++) {
        int col = warp_n * 32 + j * 8 + tig * 2;
        float bv0 = __ldg(bias + col);
        float bv1 = __ldg(bias + col + 1);
        #pragma unroll
        for (int i = 0; i < 4; i++) {
            int r0 = m0 + warp_m * 64 + i * 16 + gID;
            float* c = acc[i][j];
            if (r0 < N_NODES) {
                float2 o;
                o.x = fmaxf(c[0] + bv0, 0.f);
                o.y = fmaxf(c[1] + bv1, 0.f);
                *(float2*)(out + (size_t)r0 * FD + col) = o;
                if (out2) *(float2*)(out2 + (size_t)r0 * FD + col) = o;
            }
            int r1 = r0 + 8;
            if (r1 < N_NODES) {
                float2 o;
                o.x = fmaxf(c[2] + bv0, 0.f);
                o.y = fmaxf(c[3] + bv1, 0.f);
                *(float2*)(out + (size_t)r1 * FD + col) = o;
                if (out2) *(float2*)(out2 + (size_t)r1 * FD + col) = o;
            }
        }
    }
}

// ---- final: edge embeddings + logits (warp per edge) ----
__global__ void k_edge_out(const void* __restrict__ idx,
                           const float* __restrict__ Wf,
                           const float* __restrict__ bf,
                           float* __restrict__ logits,
                           float* __restrict__ emb) {
    int gid = blockIdx.x * blockDim.x + threadIdx.x;
    if (gid >= N_EDGES * 32) return;
    int e = gid >> 5, lane = gid & 31;
    int s, d; load_sd(idx, e, s, d);
    float4 sv = ((const float4*)g_node)[(size_t)s * 32 + lane];
    float4 dv = ((const float4*)g_node)[(size_t)d * 32 + lane];
    ((float4*)emb)[(size_t)e * 64 + lane]      = sv;
    ((float4*)emb)[(size_t)e * 64 + 32 + lane] = dv;
    const float4* wf4 = (const float4*)Wf;
    float4 w0 = __ldg(wf4 + lane);
    float4 w1 = __ldg(wf4 + 32 + lane);
    float p = sv.x*w0.x + sv.y*w0.y + sv.z*w0.z + sv.w*w0.w
            + dv.x*w1.x + dv.y*w1.y + dv.z*w1.z + dv.w*w1.w;
    #pragma unroll
    for (int o = 16; o > 0; o >>= 1) p += __shfl_down_sync(0xffffffffu, p, o);
    if (lane == 0) logits[e] = p + bf[0];
}

extern "C" void kernel_launch(void* const* d_in, const int* in_sizes, int n_in,
                              void* d_out, int out_size) {
    const float* edge_attr = (const float*)d_in[0];
    const void*  eidx      = d_in[1];
    const float* W0e = (const float*)d_in[2];
    const float* b0e = (const float*)d_in[3];
    const float* W0n = (const float*)d_in[4];
    const float* b0n = (const float*)d_in[5];
    const float* W1e = (const float*)d_in[6];
    const float* b1e = (const float*)d_in[7];
    const float* W1n = (const float*)d_in[8];
    const float* b1n = (const float*)d_in[9];
    const float* Wf  = (const float*)d_in[10];
    const float* bf  = (const float*)d_in[11];

    float* out_logits = (float*)d_out;
    float* out_emb    = out_logits + N_EDGES;
    float* out_node   = out_emb + (size_t)N_EDGES * 2 * FD;

    const int TB = 256;
    int gn  = (N_NODES + TB - 1) / TB;
    int ge  = (N_EDGES + TB - 1) / TB;
    int gw  = (N_NODES * 32 + TB - 1) / TB;
    int gsc = (N_EDGES * 32 + TB - 1) / TB;
    int ggm = (N_NODES + 127) / 128;               // 391 tiles
    int gpw = (256 * 128 + TB - 1) / TB;           // 128 blocks

    // W pre-conversion (hi/lo bf16, transposed)
    k_prep_w<<<gpw, TB>>>(W0e, 0);
    k_prep_w<<<gpw, TB>>>(W0n, 1);
    k_prep_w<<<gpw, TB>>>(W1e, 2);
    k_prep_w<<<gpw, TB>>>(W1n, 3);

    // CSR build (scan-free: atomic range allocation)
    k_detect<<<1, 32>>>((const int*)eidx);
    k_zero_cnt<<<gn, TB>>>();
    k_hist<<<ge, TB>>>(eidx);
    k_alloc<<<gn, TB>>>();
    k_fill<<<ge, TB>>>(eidx);

    // initial means (node_attr by dst, emean by src)
    k_gather_means<<<gw, TB>>>(edge_attr);

    // layer 0
    k_gemm_mma<<<ggm, TB>>>(0, b0e, 0, nullptr);
    k_gather_neigh<<<gw, TB>>>();
    k_gemm_mma<<<ggm, TB>>>(1, b0n, 1, nullptr);

    // layer 1
    k_gemm_mma<<<ggm, TB>>>(2, b1e, 0, nullptr);
    k_gather_neigh<<<gw, TB>>>();
    k_gemm_mma<<<ggm, TB>>>(3, b1n, 1, out_node);

    // outputs
    k_edge_out<<<gsc, TB>>>(eidx, Wf, bf, out_logits, out_emb);
}